// round 12
// baseline (speedup 1.0000x reference)
#include <cuda_runtime.h>
#include <math.h>

// ---------------------------------------------------------------------------
// corr[u] = Sum_t x1[t] * Re(U[(t-u) mod h]),  U = separable Dirichlet
// upsample of the coarser x2.  For h = r*m, phi(t)=0 when t%r==0 (t!=0),
// phi(0)=1 -> outputs t%r==0 are copies; others use compacted residue tables.
// phi(t) = (1/m) e^{-i pi t/h} sin(pi t m/h)/sin(pi t/h), exact via sinpif.
// R12: upA qy-sum split into lo/hi halves (2x blocks/warps; upB adds partials
// on load); upB TX 16->8 (704 blocks). corr = R11 (2048-q chunks).
// Output [2, 6*64, 7]; shifts (0,0),(0,1),(0,2),(1,0),(1,1),(2,0),(-1,1).
// ---------------------------------------------------------------------------

#define LCH 8
typedef unsigned long long u64;

__device__ float2 g_A01[16 * 128 * 256];  // y-upsampled partial (qy lo half)
__device__ float2 g_A01h[16 * 128 * 256]; // qy hi half
__device__ float2 g_A02[16 * 64 * 256];   // combo 02 (unsplit)
__device__ float2 g_A12[16 * 64 * 128];
__device__ float2 g_A12h[16 * 64 * 128];
__device__ float  g_U01[16 * 256 * 256];  // fully upsampled (real)
__device__ float  g_U02[16 * 256 * 256];
__device__ float  g_U12[16 * 128 * 128];

__constant__ int c_dx[7] = {0, 0, 0, 1, 1, 2, -1};
__constant__ int c_dy[7] = {0, 1, 2, 0, 1, 0, 1};

__device__ __forceinline__ u64 pack2(float lo, float hi) {
    u64 r; asm("mov.b64 %0, {%1, %2};" : "=l"(r) : "f"(lo), "f"(hi)); return r;
}
__device__ __forceinline__ void unpack2(u64 v, float& lo, float& hi) {
    asm("mov.b64 {%0, %1}, %2;" : "=f"(lo), "=f"(hi) : "l"(v));
}
__device__ __forceinline__ void fma2(u64& d, u64 a, u64 b) {
    asm("fma.rn.f32x2 %0, %1, %2, %3;" : "=l"(d) : "l"(a), "l"(b), "l"(d));
}
__device__ __forceinline__ u64 add2(u64 a, u64 b) {
    u64 r; asm("add.rn.f32x2 %0, %1, %2;" : "=l"(r) : "l"(a), "l"(b)); return r;
}

__device__ __forceinline__ float2 phi_val(int t, int m, float inv_h) {
    float a  = (float)t * inv_h;              // exact binary fraction
    float sm = sinpif((float)m * a);
    float sd = sinpif(a);
    float s  = sm / (sd * (float)m);
    return make_float2(cospif(a) * s, -sm / (float)m);
}

// ---- upA r=2, half of the qy reduction per block ----
template <int MM, int RS>
__device__ __forceinline__ void upA2_half(int blk, int half,
                                          const float* __restrict__ x,
                                          float2* __restrict__ A, float* smraw) {
    const int HH = 2 * MM;
    const int RTOT = (256 / MM) * RS;         // 16
    const int MH = MM / 2;
    float*  xs = smraw;                       // [MH][RTOT] transposed
    float2* ps = (float2*)(smraw + MH * RTOT);
    int tid = threadIdx.x;
    if (tid < MM) ps[tid] = phi_val(2 * tid + 1, MM, 1.f / (float)HH);
    int row0 = blk * RTOT;
    const float* xb = x + (size_t)row0 * MM + half * MH;
    for (int i = tid; i < RTOT * MH; i += 256) {
        int rr = i / MH, cc = i - rr * MH;
        xs[cc * RTOT + rr] = xb[(size_t)rr * MM + cc];
    }
    __syncthreads();
    int g = tid / MM, u = tid & (MM - 1);
    int qbase = half * MH;
    u64 arr[RS / 2], aii[RS / 2];
#pragma unroll
    for (int k = 0; k < RS / 2; ++k) { arr[k] = 0ull; aii[k] = 0ull; }
    const float* xg = xs + g * RS;
#pragma unroll 4
    for (int qy = 0; qy < MH; ++qy) {
        float2 p = ps[(u - qbase - qy) & (MM - 1)];
        u64 px2 = pack2(p.x, p.x), py2 = pack2(p.y, p.y);
        const float* col = xg + qy * RTOT;
#pragma unroll
        for (int rp = 0; rp < RS / 4; ++rp) {
            ulonglong2 vv = *(const ulonglong2*)(col + rp * 4);  // 4 rows
            fma2(arr[2 * rp],     vv.x, px2);
            fma2(arr[2 * rp + 1], vv.y, px2);
            fma2(aii[2 * rp],     vv.x, py2);
            fma2(aii[2 * rp + 1], vv.y, py2);
        }
    }
    float2* Ab = A + (size_t)row0 * HH;
    bool own = (u / MH) == half;              // copy column owned by this half
    int ul = u - qbase;
#pragma unroll
    for (int k = 0; k < RS / 2; ++k) {
        float r0, r1, i0, i1;
        unpack2(arr[k], r0, r1);
        unpack2(aii[k], i0, i1);
        int rl = g * RS + 2 * k;
        Ab[(size_t)rl * HH + 2 * u + 1]       = make_float2(r0, i0);
        Ab[(size_t)(rl + 1) * HH + 2 * u + 1] = make_float2(r1, i1);
        float c0 = 0.f, c1 = 0.f;
        if (own) { c0 = xs[ul * RTOT + rl]; c1 = xs[ul * RTOT + rl + 1]; }
        Ab[(size_t)rl * HH + 2 * u]       = make_float2(c0, 0.f);
        Ab[(size_t)(rl + 1) * HH + 2 * u] = make_float2(c1, 0.f);
    }
}

// ---- upA r=4 (combo 02, unsplit R11 body) ----
__device__ __forceinline__ void upA4_body(int blk, const float* __restrict__ x,
                                          float2* __restrict__ A, float* smraw) {
    float*  xs = smraw;                       // [64][8] transposed
    float2* ps = (float2*)(smraw + 512);      // 192
    int tid = threadIdx.x;
    if (tid < 192)
        ps[tid] = phi_val(4 * (tid & 63) + (tid >> 6) + 1, 64, 1.f / 256.f);
    int row0 = blk * 8;
    const float* xb = x + (size_t)row0 * 64;
    for (int i = tid; i < 512; i += 256)
        xs[(i & 63) * 8 + (i >> 6)] = xb[i];
    __syncthreads();
    float2* Ab = A + (size_t)row0 * 256;
    if (tid < 192) {
        int cls = tid >> 6, u = tid & 63;
        const float2* pc = ps + cls * 64;
        u64 arr[4], aii[4];
#pragma unroll
        for (int k = 0; k < 4; ++k) { arr[k] = 0ull; aii[k] = 0ull; }
#pragma unroll 4
        for (int qy = 0; qy < 64; ++qy) {
            float2 p = pc[(u - qy) & 63];
            u64 px2 = pack2(p.x, p.x), py2 = pack2(p.y, p.y);
            const float* col = xs + qy * 8;
            ulonglong2 v0 = *(const ulonglong2*)(col);
            ulonglong2 v1 = *(const ulonglong2*)(col + 4);
            fma2(arr[0], v0.x, px2); fma2(arr[1], v0.y, px2);
            fma2(arr[2], v1.x, px2); fma2(arr[3], v1.y, px2);
            fma2(aii[0], v0.x, py2); fma2(aii[1], v0.y, py2);
            fma2(aii[2], v1.x, py2); fma2(aii[3], v1.y, py2);
        }
        int ty = 4 * u + cls + 1;
#pragma unroll
        for (int k = 0; k < 4; ++k) {
            float r0, r1, i0, i1;
            unpack2(arr[k], r0, r1);
            unpack2(aii[k], i0, i1);
            Ab[(size_t)(2 * k) * 256 + ty]     = make_float2(r0, i0);
            Ab[(size_t)(2 * k + 1) * 256 + ty] = make_float2(r1, i1);
        }
    } else {
        int u = tid - 192;
#pragma unroll
        for (int rr = 0; rr < 8; ++rr)
            Ab[(size_t)rr * 256 + 4 * u] = make_float2(xs[u * 8 + rr], 0.f);
    }
}

__global__ void __launch_bounds__(256) upA_kernel(const float* __restrict__ x1,
                                                  const float* __restrict__ x2) {
    extern __shared__ float smraw[];
    int bx = blockIdx.x;
    if (bx < 128)      upA2_half<128, 8>(bx, 0, x1, g_A01, smraw);
    else if (bx < 256) upA2_half<128, 8>(bx - 128, 1, x1, g_A01h, smraw);
    else if (bx < 384) upA4_body(bx - 256, x2, g_A02, smraw);
    else if (bx < 448) upA2_half<64, 4>(bx - 384, 0, x2, g_A12, smraw);
    else               upA2_half<64, 4>(bx - 448, 1, x2, g_A12h, smraw);
}

// ---- upB r=2: TX=8, lo+hi partial add, qx-paired aligned LDS.128 window ----
template <int MM>
__device__ __forceinline__ void upB2_core8(int img, int t0, int ty,
                                           const float2* __restrict__ Alo,
                                           const float2* __restrict__ Ahi,
                                           float* __restrict__ U,
                                           const float2* ps) {
    const int HH = 2 * MM;
    u64 acc2[8];
#pragma unroll
    for (int i = 0; i < 8; ++i) acc2[i] = 0ull;
    const u64* lo = (const u64*)Alo + (size_t)img * MM * HH + ty;
    const u64* hi = (const u64*)Ahi + (size_t)img * MM * HH + ty;
    float* Ub = U + (size_t)img * HH * HH;
    for (int qx = 0; qx < MM; qx += 2) {
        u64 a2 = add2(lo[(size_t)qx * HH], hi[(size_t)qx * HH]);
        u64 b2 = add2(lo[(size_t)(qx + 1) * HH], hi[(size_t)(qx + 1) * HH]);
        if ((unsigned)(qx - t0) < 8u) {
            float l, h; unpack2(a2, l, h);
            Ub[(size_t)(2 * qx) * HH + ty] = l;            // copy row
        }
        if ((unsigned)(qx + 1 - t0) < 8u) {
            float l, h; unpack2(b2, l, h);
            Ub[(size_t)(2 * (qx + 1)) * HH + ty] = l;
        }
        int k0 = (t0 - qx) & (MM - 1);                     // even
        const ulonglong2* pw = (const ulonglong2*)(ps + k0);
        u64 W[8];
#pragma unroll
        for (int m2 = 0; m2 < 4; ++m2) { ulonglong2 t = pw[m2]; W[2 * m2] = t.x; W[2 * m2 + 1] = t.y; }
        u64 ea = *(const u64*)(ps + ((k0 - 1) & (MM - 1)));
        fma2(acc2[0], b2, ea);
#pragma unroll
        for (int i = 0; i < 8; ++i) fma2(acc2[i], a2, W[i]);
#pragma unroll
        for (int i = 1; i < 8; ++i) fma2(acc2[i], b2, W[i - 1]);
    }
#pragma unroll
    for (int i = 0; i < 8; ++i) {
        float l, h; unpack2(acc2[i], l, h);
        Ub[(size_t)(2 * (t0 + i) + 1) * HH + ty] = l - h;
    }
}

// ---- upB r=4 (combo 02): TX=8, single A ----
__device__ __forceinline__ void upB4_core8(int img, int t0, int cls, int ty,
                                           const float2* __restrict__ A,
                                           float* __restrict__ U,
                                           const float2* ps) {
    u64 acc2[8];
#pragma unroll
    for (int i = 0; i < 8; ++i) acc2[i] = 0ull;
    const u64* Ab64 = (const u64*)A + (size_t)img * 64 * 256 + ty;
    float* Ub = U + (size_t)img * 256 * 256;
    for (int qx = 0; qx < 64; qx += 2) {
        u64 a2 = Ab64[(size_t)qx * 256];
        u64 b2 = Ab64[(size_t)(qx + 1) * 256];
        if (cls == 0 && (unsigned)(qx - t0) < 8u) {
            float l, h; unpack2(a2, l, h);
            Ub[(size_t)(4 * qx) * 256 + ty] = l;
        }
        if (cls == 0 && (unsigned)(qx + 1 - t0) < 8u) {
            float l, h; unpack2(b2, l, h);
            Ub[(size_t)(4 * (qx + 1)) * 256 + ty] = l;
        }
        int k0 = (t0 - qx) & 63;                           // even
        const ulonglong2* pw = (const ulonglong2*)(ps + k0);
        u64 W[8];
#pragma unroll
        for (int m2 = 0; m2 < 4; ++m2) { ulonglong2 t = pw[m2]; W[2 * m2] = t.x; W[2 * m2 + 1] = t.y; }
        u64 ea = *(const u64*)(ps + ((k0 - 1) & 63));
        fma2(acc2[0], b2, ea);
#pragma unroll
        for (int i = 0; i < 8; ++i) fma2(acc2[i], a2, W[i]);
#pragma unroll
        for (int i = 1; i < 8; ++i) fma2(acc2[i], b2, W[i - 1]);
    }
#pragma unroll
    for (int i = 0; i < 8; ++i) {
        float l, h; unpack2(acc2[i], l, h);
        Ub[(size_t)(4 * (t0 + i) + cls + 1) * 256 + ty] = l - h;
    }
}

__global__ void __launch_bounds__(256) upB_kernel() {
    extern __shared__ float smraw[];
    float2* ps = (float2*)smraw;
    int bx = blockIdx.x, tid = threadIdx.x;
    if (bx < 256) {                            // upB01: MM=128, TX=8
        int img = bx >> 4, t0 = (bx & 15) * 8;
        if (tid < 128) { float2 v = phi_val(2 * tid + 1, 128, 1.f / 256.f); ps[tid] = v; ps[tid + 128] = v; }
        __syncthreads();
        upB2_core8<128>(img, t0, tid, g_A01, g_A01h, g_U01, ps);
        return;
    }
    bx -= 256;
    if (bx < 384) {                            // upB02: r=4, TX=8
        int img = bx / 24, r = bx % 24, cls = r >> 3, t0 = (r & 7) * 8;
        if (tid < 64) { float2 v = phi_val(4 * tid + cls + 1, 64, 1.f / 256.f); ps[tid] = v; ps[tid + 64] = v; }
        __syncthreads();
        upB4_core8(img, t0, cls, tid, g_A02, g_U02, ps);
        return;
    }
    bx -= 384;                                 // upB12: 2 images per block
    {
        int imgp = bx >> 3, t0 = (bx & 7) * 8;
        if (tid < 64) { float2 v = phi_val(2 * tid + 1, 64, 1.f / 128.f); ps[tid] = v; ps[tid + 64] = v; }
        __syncthreads();
        upB2_core8<64>(imgp * 2 + (tid >> 7), t0, tid & 127, g_A12, g_A12h, g_U12, ps);
    }
}

// ---- corr body (R11, unchanged): 2048-q chunks, 2-q vector loads ----
__device__ __forceinline__ void corr_body(const float* __restrict__ A,
                                          const float* __restrict__ B,
                                          float* __restrict__ out,
                                          int lm, int qblk, int s, int b,
                                          int sg, int trans, int pbase,
                                          float* smraw) {
    int h = 1 << lm, hh = h * h, hm = h - 1;
    int dx = sg * c_dx[s], dy = sg * c_dy[s];
    const float* Ab = A + (size_t)b * LCH * hh;
    const float* Bb = B + (size_t)b * LCH * hh;
    int q0 = qblk * 2048;
    int dyEven = !(dy & 1);
    u64 acc2[32];
#pragma unroll
    for (int k = 0; k < 32; ++k) acc2[k] = 0ull;
    for (int q = q0 + threadIdx.x * 2; q < q0 + 2048; q += 256) {
        int qx = q >> lm, qy = q & hm;                 // qy even
        int fx  = ((qx + dx) & hm) << lm;
        int fya = (qy + dy) & hm;
        int fyb = (qy + 1 + dy) & hm;
        float a_a[8], a_b[8];
        if (dyEven) {
#pragma unroll
            for (int l = 0; l < 8; ++l) {
                float2 av = *(const float2*)&Ab[(size_t)l * hh + fx + fya];
                a_a[l] = av.x; a_b[l] = av.y;
            }
        } else {
#pragma unroll
            for (int l = 0; l < 8; ++l) {
                a_a[l] = Ab[(size_t)l * hh + fx + fya];
                a_b[l] = Ab[(size_t)l * hh + fx + fyb];
            }
        }
        float2 cc[8];
#pragma unroll
        for (int j = 0; j < 8; ++j)
            cc[j] = *(const float2*)&Bb[(size_t)j * hh + q];
        u64 c2a[4], c2b[4];
#pragma unroll
        for (int jj = 0; jj < 4; ++jj) {
            c2a[jj] = pack2(cc[2 * jj].x, cc[2 * jj + 1].x);
            c2b[jj] = pack2(cc[2 * jj].y, cc[2 * jj + 1].y);
        }
#pragma unroll
        for (int i = 0; i < 8; ++i) {
            u64 a2a = pack2(a_a[i], a_a[i]);
            u64 a2b = pack2(a_b[i], a_b[i]);
#pragma unroll
            for (int jj = 0; jj < 4; ++jj) {
                fma2(acc2[i * 4 + jj], a2a, c2a[jj]);
                fma2(acc2[i * 4 + jj], a2b, c2b[jj]);
            }
        }
    }
    u64* red = (u64*)smraw;
    int lane = threadIdx.x & 31;
    int wid  = threadIdx.x >> 5;
#pragma unroll
    for (int k = 0; k < 32; ++k) {
        u64 v = acc2[k];
        v = add2(v, __shfl_down_sync(0xffffffffu, v, 16));
        v = add2(v, __shfl_down_sync(0xffffffffu, v, 8));
        v = add2(v, __shfl_down_sync(0xffffffffu, v, 4));
        v = add2(v, __shfl_down_sync(0xffffffffu, v, 2));
        v = add2(v, __shfl_down_sync(0xffffffffu, v, 1));
        if (lane == 0) red[k * 4 + wid] = v;
    }
    __syncthreads();
    if (threadIdx.x < 32) {
        u64 sum = red[threadIdx.x * 4];
        sum = add2(sum, red[threadIdx.x * 4 + 1]);
        sum = add2(sum, red[threadIdx.x * 4 + 2]);
        sum = add2(sum, red[threadIdx.x * 4 + 3]);
        float lo, hi; unpack2(sum, lo, hi);
        int i = threadIdx.x >> 2, j0 = (threadIdx.x & 3) * 2;
        int p0 = trans ? (j0 * 8 + i) : (i * 8 + j0);
        int p1 = trans ? ((j0 + 1) * 8 + i) : (i * 8 + j0 + 1);
        atomicAdd(&out[(size_t)b * 2688 + (size_t)(pbase + p0) * 7 + s], lo);
        atomicAdd(&out[(size_t)b * 2688 + (size_t)(pbase + p1) * 7 + s], hi);
    }
}

__global__ void __launch_bounds__(128) corr_kernel(const float* __restrict__ x0,
                                                   const float* __restrict__ x1,
                                                   const float* __restrict__ x2,
                                                   float* __restrict__ out) {
    extern __shared__ float smraw[];
    int bx = blockIdx.x, s = blockIdx.y, b = blockIdx.z;
    if (bx < 32)       corr_body(x0,    x0, out, 8, bx,       s, b,  1, 0, 0,   smraw);
    else if (bx < 64)  corr_body(g_U01, x0, out, 8, bx - 32,  s, b, -1, 1, 64,  smraw);
    else if (bx < 96)  corr_body(g_U02, x0, out, 8, bx - 64,  s, b, -1, 1, 128, smraw);
    else if (bx < 104) corr_body(x1,    x1, out, 7, bx - 96,  s, b,  1, 0, 192, smraw);
    else if (bx < 112) corr_body(g_U12, x1, out, 7, bx - 104, s, b, -1, 1, 256, smraw);
    else               corr_body(x2,    x2, out, 6, bx - 112, s, b,  1, 0, 320, smraw);
}

extern "C" void kernel_launch(void* const* d_in, const int* in_sizes, int n_in,
                              void* d_out, int out_size) {
    const float* x0 = nullptr;
    const float* x1 = nullptr;
    const float* x2 = nullptr;
    for (int i = 0; i < n_in; ++i) {
        if (in_sizes[i] == 2 * 8 * 256 * 256)      x0 = (const float*)d_in[i];
        else if (in_sizes[i] == 2 * 8 * 128 * 128) x1 = (const float*)d_in[i];
        else if (in_sizes[i] == 2 * 8 * 64 * 64)   x2 = (const float*)d_in[i];
    }
    float* out = (float*)d_out;

    cudaMemsetAsync(d_out, 0, (size_t)out_size * sizeof(float));
    upA_kernel<<<512, 256, 5120>>>(x1, x2);
    upB_kernel<<<704, 256, 2048>>>();
    corr_kernel<<<dim3(114, 7, 2), 128, 1024>>>(x0, x1, x2, out);
}

// round 13
// speedup vs baseline: 1.0257x; 1.0257x over previous
#include <cuda_runtime.h>
#include <math.h>

// ---------------------------------------------------------------------------
// corr[u] = Sum_t x1[t] * Re(U[(t-u) mod h]),  U = separable Dirichlet
// upsample of the coarser x2.  For h = r*m, phi(t)=0 when t%r==0 (t!=0),
// phi(0)=1 -> outputs t%r==0 are copies; others use compacted residue tables.
// phi(t) = (1/m) e^{-i pi t/h} sin(pi t m/h)/sin(pi t/h), exact via sinpif.
// R13 = R11 with ONE change: upA phi tables pre-packed {re,re,im,im} (16B)
// so the per-tap LDS.64 + 4 MOV packs become a single LDS.128.
// Output [2, 6*64, 7]; shifts (0,0),(0,1),(0,2),(1,0),(1,1),(2,0),(-1,1).
// ---------------------------------------------------------------------------

#define LCH 8
typedef unsigned long long u64;

__device__ float2 g_A01[16 * 128 * 256]; // y-upsampled (complex)
__device__ float2 g_A02[16 * 64 * 256];
__device__ float2 g_A12[16 * 64 * 128];
__device__ float  g_U01[16 * 256 * 256]; // fully upsampled (real)
__device__ float  g_U02[16 * 256 * 256];
__device__ float  g_U12[16 * 128 * 128];

__constant__ int c_dx[7] = {0, 0, 0, 1, 1, 2, -1};
__constant__ int c_dy[7] = {0, 1, 2, 0, 1, 0, 1};

__device__ __forceinline__ u64 pack2(float lo, float hi) {
    u64 r; asm("mov.b64 %0, {%1, %2};" : "=l"(r) : "f"(lo), "f"(hi)); return r;
}
__device__ __forceinline__ void unpack2(u64 v, float& lo, float& hi) {
    asm("mov.b64 {%0, %1}, %2;" : "=f"(lo), "=f"(hi) : "l"(v));
}
__device__ __forceinline__ void fma2(u64& d, u64 a, u64 b) {
    asm("fma.rn.f32x2 %0, %1, %2, %3;" : "=l"(d) : "l"(a), "l"(b), "l"(d));
}
__device__ __forceinline__ u64 add2(u64 a, u64 b) {
    u64 r; asm("add.rn.f32x2 %0, %1, %2;" : "=l"(r) : "l"(a), "l"(b)); return r;
}

__device__ __forceinline__ float2 phi_val(int t, int m, float inv_h) {
    float a  = (float)t * inv_h;              // exact binary fraction
    float sm = sinpif((float)m * a);
    float sd = sinpif(a);
    float s  = sm / (sd * (float)m);
    return make_float2(cospif(a) * s, -sm / (float)m);
}

// ---- upA r=2: pre-packed phi {re,re,im,im}; transposed smem x tile ----
template <int MM, int RS>
__device__ __forceinline__ void upA2_body(int blk, const float* __restrict__ x,
                                          float2* __restrict__ A, float* smraw) {
    const int HH = 2 * MM;
    const int RTOT = (256 / MM) * RS;         // 16
    u64*   ps2 = (u64*)smraw;                 // [MM]: {re,re},{im,im}
    float* xs  = smraw + 4 * MM;              // [MM][RTOT] transposed
    int tid = threadIdx.x;
    if (tid < MM) {
        float2 v = phi_val(2 * tid + 1, MM, 1.f / (float)HH);
        ps2[2 * tid]     = pack2(v.x, v.x);
        ps2[2 * tid + 1] = pack2(v.y, v.y);
    }
    int row0 = blk * RTOT;
    const float* xb = x + (size_t)row0 * MM;
#pragma unroll
    for (int i = tid; i < RTOT * MM; i += 256)
        xs[(i & (MM - 1)) * RTOT + (i / MM)] = xb[i];
    __syncthreads();
    int g = tid / MM, u = tid & (MM - 1);
    u64 arr[RS / 2], aii[RS / 2];
#pragma unroll
    for (int k = 0; k < RS / 2; ++k) { arr[k] = 0ull; aii[k] = 0ull; }
    const float* xg = xs + g * RS;
#pragma unroll 4
    for (int qy = 0; qy < MM; ++qy) {
        ulonglong2 pv = *(const ulonglong2*)&ps2[2 * ((u - qy) & (MM - 1))];
        const float* col = xg + qy * RTOT;
#pragma unroll
        for (int rp = 0; rp < RS / 4; ++rp) {
            ulonglong2 vv = *(const ulonglong2*)(col + rp * 4);  // 4 rows
            fma2(arr[2 * rp],     vv.x, pv.x);
            fma2(arr[2 * rp + 1], vv.y, pv.x);
            fma2(aii[2 * rp],     vv.x, pv.y);
            fma2(aii[2 * rp + 1], vv.y, pv.y);
        }
    }
    float2* Ab = A + (size_t)row0 * HH;
#pragma unroll
    for (int k = 0; k < RS / 2; ++k) {
        float r0, r1, i0, i1;
        unpack2(arr[k], r0, r1);
        unpack2(aii[k], i0, i1);
        int rl = g * RS + 2 * k;
        Ab[(size_t)rl * HH + 2 * u + 1]       = make_float2(r0, i0);
        Ab[(size_t)(rl + 1) * HH + 2 * u + 1] = make_float2(r1, i1);
        Ab[(size_t)rl * HH + 2 * u]       = make_float2(xs[u * RTOT + rl], 0.f);
        Ab[(size_t)(rl + 1) * HH + 2 * u] = make_float2(xs[u * RTOT + rl + 1], 0.f);
    }
}

// ---- upA r=4 (combo 02): pre-packed phi; tids 192-255 write copies ----
__device__ __forceinline__ void upA4_body(int blk, const float* __restrict__ x,
                                          float2* __restrict__ A, float* smraw) {
    u64*   ps2 = (u64*)smraw;                 // 192 entries x {re,re},{im,im}
    float* xs  = smraw + 4 * 192;             // [64][8] transposed
    int tid = threadIdx.x;
    if (tid < 192) {
        float2 v = phi_val(4 * (tid & 63) + (tid >> 6) + 1, 64, 1.f / 256.f);
        ps2[2 * tid]     = pack2(v.x, v.x);
        ps2[2 * tid + 1] = pack2(v.y, v.y);
    }
    int row0 = blk * 8;
    const float* xb = x + (size_t)row0 * 64;
    for (int i = tid; i < 512; i += 256)
        xs[(i & 63) * 8 + (i >> 6)] = xb[i];
    __syncthreads();
    float2* Ab = A + (size_t)row0 * 256;
    if (tid < 192) {
        int cls = tid >> 6, u = tid & 63;
        const u64* pc2 = ps2 + cls * 128;
        u64 arr[4], aii[4];
#pragma unroll
        for (int k = 0; k < 4; ++k) { arr[k] = 0ull; aii[k] = 0ull; }
#pragma unroll 4
        for (int qy = 0; qy < 64; ++qy) {
            ulonglong2 pv = *(const ulonglong2*)&pc2[2 * ((u - qy) & 63)];
            const float* col = xs + qy * 8;
            ulonglong2 v0 = *(const ulonglong2*)(col);
            ulonglong2 v1 = *(const ulonglong2*)(col + 4);
            fma2(arr[0], v0.x, pv.x); fma2(arr[1], v0.y, pv.x);
            fma2(arr[2], v1.x, pv.x); fma2(arr[3], v1.y, pv.x);
            fma2(aii[0], v0.x, pv.y); fma2(aii[1], v0.y, pv.y);
            fma2(aii[2], v1.x, pv.y); fma2(aii[3], v1.y, pv.y);
        }
        int ty = 4 * u + cls + 1;
#pragma unroll
        for (int k = 0; k < 4; ++k) {
            float r0, r1, i0, i1;
            unpack2(arr[k], r0, r1);
            unpack2(aii[k], i0, i1);
            Ab[(size_t)(2 * k) * 256 + ty]     = make_float2(r0, i0);
            Ab[(size_t)(2 * k + 1) * 256 + ty] = make_float2(r1, i1);
        }
    } else {
        int u = tid - 192;
#pragma unroll
        for (int rr = 0; rr < 8; ++rr)
            Ab[(size_t)rr * 256 + 4 * u] = make_float2(xs[u * 8 + rr], 0.f);
    }
}

__global__ void __launch_bounds__(256) upA_kernel(const float* __restrict__ x1,
                                                  const float* __restrict__ x2) {
    extern __shared__ float smraw[];
    int bx = blockIdx.x;
    if (bx < 128)      upA2_body<128, 8>(bx, x1, g_A01, smraw);
    else if (bx < 256) upA4_body(bx - 128, x2, g_A02, smraw);
    else               upA2_body<64, 4>(bx - 256, x2, g_A12, smraw);
}

// ---- upB r=2 (R11 body): qx-paired, aligned LDS.128 window ----
template <int MM, int TX>   // TX must be 16
__device__ __forceinline__ void upB2_core(int img, int t0, int ty,
                                          const float2* __restrict__ A,
                                          float* __restrict__ U,
                                          const float2* ps) {
    const int HH = 2 * MM;
    u64 acc2[TX];
#pragma unroll
    for (int i = 0; i < TX; ++i) acc2[i] = 0ull;
    const float2* Ab = A + (size_t)img * MM * HH + ty;
    float* Ub = U + (size_t)img * HH * HH;
    for (int qx = 0; qx < MM; qx += 2) {
        float2 av_a = Ab[(size_t)qx * HH];
        float2 av_b = Ab[(size_t)(qx + 1) * HH];
        if ((unsigned)(qx - t0) < (unsigned)TX)
            Ub[(size_t)(2 * qx) * HH + ty] = av_a.x;
        if ((unsigned)(qx + 1 - t0) < (unsigned)TX)
            Ub[(size_t)(2 * (qx + 1)) * HH + ty] = av_b.x;
        int k0 = (t0 - qx) & (MM - 1);                 // even
        const ulonglong2* pw = (const ulonglong2*)(ps + k0);
        u64 W[16];
#pragma unroll
        for (int m2 = 0; m2 < 8; ++m2) { ulonglong2 t = pw[m2]; W[2 * m2] = t.x; W[2 * m2 + 1] = t.y; }
        u64 ea = *(const u64*)(ps + ((k0 - 1) & (MM - 1)));
        u64 a2 = pack2(av_a.x, av_a.y);
        u64 b2 = pack2(av_b.x, av_b.y);
        fma2(acc2[0], b2, ea);
#pragma unroll
        for (int i = 0; i < 16; ++i) fma2(acc2[i], a2, W[i]);
#pragma unroll
        for (int i = 1; i < 16; ++i) fma2(acc2[i], b2, W[i - 1]);
    }
#pragma unroll
    for (int i = 0; i < TX; ++i) {
        float lo, hi; unpack2(acc2[i], lo, hi);
        Ub[(size_t)(2 * (t0 + i) + 1) * HH + ty] = lo - hi;
    }
}

// ---- upB r=4 (R11 body) ----
__device__ __forceinline__ void upB4_core(int img, int t0, int cls, int ty,
                                          const float2* __restrict__ A,
                                          float* __restrict__ U,
                                          const float2* ps) {
    u64 acc2[16];
#pragma unroll
    for (int i = 0; i < 16; ++i) acc2[i] = 0ull;
    const float2* Ab = A + (size_t)img * 64 * 256 + ty;
    float* Ub = U + (size_t)img * 256 * 256;
    for (int qx = 0; qx < 64; qx += 2) {
        float2 av_a = Ab[(size_t)qx * 256];
        float2 av_b = Ab[(size_t)(qx + 1) * 256];
        if (cls == 0 && (unsigned)(qx - t0) < 16u)
            Ub[(size_t)(4 * qx) * 256 + ty] = av_a.x;
        if (cls == 0 && (unsigned)(qx + 1 - t0) < 16u)
            Ub[(size_t)(4 * (qx + 1)) * 256 + ty] = av_b.x;
        int k0 = (t0 - qx) & 63;                       // even
        const ulonglong2* pw = (const ulonglong2*)(ps + k0);
        u64 W[16];
#pragma unroll
        for (int m2 = 0; m2 < 8; ++m2) { ulonglong2 t = pw[m2]; W[2 * m2] = t.x; W[2 * m2 + 1] = t.y; }
        u64 ea = *(const u64*)(ps + ((k0 - 1) & 63));
        u64 a2 = pack2(av_a.x, av_a.y);
        u64 b2 = pack2(av_b.x, av_b.y);
        fma2(acc2[0], b2, ea);
#pragma unroll
        for (int i = 0; i < 16; ++i) fma2(acc2[i], a2, W[i]);
#pragma unroll
        for (int i = 1; i < 16; ++i) fma2(acc2[i], b2, W[i - 1]);
    }
#pragma unroll
    for (int i = 0; i < 16; ++i) {
        float lo, hi; unpack2(acc2[i], lo, hi);
        Ub[(size_t)(4 * (t0 + i) + cls + 1) * 256 + ty] = lo - hi;
    }
}

__global__ void __launch_bounds__(256) upB_kernel() {
    extern __shared__ float smraw[];
    float2* ps = (float2*)smraw;
    int bx = blockIdx.x, tid = threadIdx.x;
    if (bx < 128) {                            // upB01: MM=128, TX=16
        int img = bx >> 3, t0 = (bx & 7) * 16;
        if (tid < 128) { float2 v = phi_val(2 * tid + 1, 128, 1.f / 256.f); ps[tid] = v; ps[tid + 128] = v; }
        __syncthreads();
        upB2_core<128, 16>(img, t0, tid, g_A01, g_U01, ps);
        return;
    }
    bx -= 128;
    if (bx < 192) {                            // upB02: r=4
        int img = bx / 12, r = bx % 12, cls = r >> 2, t0 = (r & 3) * 16;
        if (tid < 64) { float2 v = phi_val(4 * tid + cls + 1, 64, 1.f / 256.f); ps[tid] = v; ps[tid + 64] = v; }
        __syncthreads();
        upB4_core(img, t0, cls, tid, g_A02, g_U02, ps);
        return;
    }
    bx -= 192;                                 // upB12: 2 images per block
    {
        int imgp = bx >> 2, t0 = (bx & 3) * 16;
        if (tid < 64) { float2 v = phi_val(2 * tid + 1, 64, 1.f / 128.f); ps[tid] = v; ps[tid + 64] = v; }
        __syncthreads();
        upB2_core<64, 16>(imgp * 2 + (tid >> 7), t0, tid & 127, g_A12, g_U12, ps);
    }
}

// ---- corr body (R11, unchanged): 2048-q chunks, 2-q vector loads ----
__device__ __forceinline__ void corr_body(const float* __restrict__ A,
                                          const float* __restrict__ B,
                                          float* __restrict__ out,
                                          int lm, int qblk, int s, int b,
                                          int sg, int trans, int pbase,
                                          float* smraw) {
    int h = 1 << lm, hh = h * h, hm = h - 1;
    int dx = sg * c_dx[s], dy = sg * c_dy[s];
    const float* Ab = A + (size_t)b * LCH * hh;
    const float* Bb = B + (size_t)b * LCH * hh;
    int q0 = qblk * 2048;
    int dyEven = !(dy & 1);
    u64 acc2[32];
#pragma unroll
    for (int k = 0; k < 32; ++k) acc2[k] = 0ull;
    for (int q = q0 + threadIdx.x * 2; q < q0 + 2048; q += 256) {
        int qx = q >> lm, qy = q & hm;                 // qy even
        int fx  = ((qx + dx) & hm) << lm;
        int fya = (qy + dy) & hm;
        int fyb = (qy + 1 + dy) & hm;
        float a_a[8], a_b[8];
        if (dyEven) {
#pragma unroll
            for (int l = 0; l < 8; ++l) {
                float2 av = *(const float2*)&Ab[(size_t)l * hh + fx + fya];
                a_a[l] = av.x; a_b[l] = av.y;
            }
        } else {
#pragma unroll
            for (int l = 0; l < 8; ++l) {
                a_a[l] = Ab[(size_t)l * hh + fx + fya];
                a_b[l] = Ab[(size_t)l * hh + fx + fyb];
            }
        }
        float2 cc[8];
#pragma unroll
        for (int j = 0; j < 8; ++j)
            cc[j] = *(const float2*)&Bb[(size_t)j * hh + q];
        u64 c2a[4], c2b[4];
#pragma unroll
        for (int jj = 0; jj < 4; ++jj) {
            c2a[jj] = pack2(cc[2 * jj].x, cc[2 * jj + 1].x);
            c2b[jj] = pack2(cc[2 * jj].y, cc[2 * jj + 1].y);
        }
#pragma unroll
        for (int i = 0; i < 8; ++i) {
            u64 a2a = pack2(a_a[i], a_a[i]);
            u64 a2b = pack2(a_b[i], a_b[i]);
#pragma unroll
            for (int jj = 0; jj < 4; ++jj) {
                fma2(acc2[i * 4 + jj], a2a, c2a[jj]);
                fma2(acc2[i * 4 + jj], a2b, c2b[jj]);
            }
        }
    }
    u64* red = (u64*)smraw;
    int lane = threadIdx.x & 31;
    int wid  = threadIdx.x >> 5;
#pragma unroll
    for (int k = 0; k < 32; ++k) {
        u64 v = acc2[k];
        v = add2(v, __shfl_down_sync(0xffffffffu, v, 16));
        v = add2(v, __shfl_down_sync(0xffffffffu, v, 8));
        v = add2(v, __shfl_down_sync(0xffffffffu, v, 4));
        v = add2(v, __shfl_down_sync(0xffffffffu, v, 2));
        v = add2(v, __shfl_down_sync(0xffffffffu, v, 1));
        if (lane == 0) red[k * 4 + wid] = v;
    }
    __syncthreads();
    if (threadIdx.x < 32) {
        u64 sum = red[threadIdx.x * 4];
        sum = add2(sum, red[threadIdx.x * 4 + 1]);
        sum = add2(sum, red[threadIdx.x * 4 + 2]);
        sum = add2(sum, red[threadIdx.x * 4 + 3]);
        float lo, hi; unpack2(sum, lo, hi);
        int i = threadIdx.x >> 2, j0 = (threadIdx.x & 3) * 2;
        int p0 = trans ? (j0 * 8 + i) : (i * 8 + j0);
        int p1 = trans ? ((j0 + 1) * 8 + i) : (i * 8 + j0 + 1);
        atomicAdd(&out[(size_t)b * 2688 + (size_t)(pbase + p0) * 7 + s], lo);
        atomicAdd(&out[(size_t)b * 2688 + (size_t)(pbase + p1) * 7 + s], hi);
    }
}

__global__ void __launch_bounds__(128) corr_kernel(const float* __restrict__ x0,
                                                   const float* __restrict__ x1,
                                                   const float* __restrict__ x2,
                                                   float* __restrict__ out) {
    extern __shared__ float smraw[];
    int bx = blockIdx.x, s = blockIdx.y, b = blockIdx.z;
    if (bx < 32)       corr_body(x0,    x0, out, 8, bx,       s, b,  1, 0, 0,   smraw);
    else if (bx < 64)  corr_body(g_U01, x0, out, 8, bx - 32,  s, b, -1, 1, 64,  smraw);
    else if (bx < 96)  corr_body(g_U02, x0, out, 8, bx - 64,  s, b, -1, 1, 128, smraw);
    else if (bx < 104) corr_body(x1,    x1, out, 7, bx - 96,  s, b,  1, 0, 192, smraw);
    else if (bx < 112) corr_body(g_U12, x1, out, 7, bx - 104, s, b, -1, 1, 256, smraw);
    else               corr_body(x2,    x2, out, 6, bx - 112, s, b,  1, 0, 320, smraw);
}

extern "C" void kernel_launch(void* const* d_in, const int* in_sizes, int n_in,
                              void* d_out, int out_size) {
    const float* x0 = nullptr;
    const float* x1 = nullptr;
    const float* x2 = nullptr;
    for (int i = 0; i < n_in; ++i) {
        if (in_sizes[i] == 2 * 8 * 256 * 256)      x0 = (const float*)d_in[i];
        else if (in_sizes[i] == 2 * 8 * 128 * 128) x1 = (const float*)d_in[i];
        else if (in_sizes[i] == 2 * 8 * 64 * 64)   x2 = (const float*)d_in[i];
    }
    float* out = (float*)d_out;

    cudaMemsetAsync(d_out, 0, (size_t)out_size * sizeof(float));
    upA_kernel<<<320, 256, 10240>>>(x1, x2);
    upB_kernel<<<352, 256, 2048>>>();
    corr_kernel<<<dim3(114, 7, 2), 128, 1024>>>(x0, x1, x2, out);
}

// round 14
// speedup vs baseline: 1.1017x; 1.0741x over previous
#include <cuda_runtime.h>
#include <math.h>

// ---------------------------------------------------------------------------
// corr[u] = Sum_t x1[t] * Re(U[(t-u) mod h]),  U = separable Dirichlet
// upsample of the coarser x2.  For h = r*m, phi(t)=0 when t%r==0 (t!=0),
// phi(0)=1 -> outputs t%r==0 are copies; others use compacted residue tables.
// phi(t) = (1/m) e^{-i pi t/h} sin(pi t m/h)/sin(pi t/h), exact via sinpif.
// R14 = R11 with: (a) d_out zeroing folded into upA (drops the memset launch
// node), (b) upA qy unroll 4 -> 8 (deeper LDS pipelining).
// Output [2, 6*64, 7]; shifts (0,0),(0,1),(0,2),(1,0),(1,1),(2,0),(-1,1).
// ---------------------------------------------------------------------------

#define LCH 8
typedef unsigned long long u64;

__device__ float2 g_A01[16 * 128 * 256]; // y-upsampled (complex)
__device__ float2 g_A02[16 * 64 * 256];
__device__ float2 g_A12[16 * 64 * 128];
__device__ float  g_U01[16 * 256 * 256]; // fully upsampled (real)
__device__ float  g_U02[16 * 256 * 256];
__device__ float  g_U12[16 * 128 * 128];

__constant__ int c_dx[7] = {0, 0, 0, 1, 1, 2, -1};
__constant__ int c_dy[7] = {0, 1, 2, 0, 1, 0, 1};

__device__ __forceinline__ u64 pack2(float lo, float hi) {
    u64 r; asm("mov.b64 %0, {%1, %2};" : "=l"(r) : "f"(lo), "f"(hi)); return r;
}
__device__ __forceinline__ void unpack2(u64 v, float& lo, float& hi) {
    asm("mov.b64 {%0, %1}, %2;" : "=f"(lo), "=f"(hi) : "l"(v));
}
__device__ __forceinline__ void fma2(u64& d, u64 a, u64 b) {
    asm("fma.rn.f32x2 %0, %1, %2, %3;" : "=l"(d) : "l"(a), "l"(b), "l"(d));
}
__device__ __forceinline__ u64 add2(u64 a, u64 b) {
    u64 r; asm("add.rn.f32x2 %0, %1, %2;" : "=l"(r) : "l"(a), "l"(b)); return r;
}

__device__ __forceinline__ float2 phi_val(int t, int m, float inv_h) {
    float a  = (float)t * inv_h;              // exact binary fraction
    float sm = sinpif((float)m * a);
    float sd = sinpif(a);
    float s  = sm / (sd * (float)m);
    return make_float2(cospif(a) * s, -sm / (float)m);
}

// ---- upA r=2 (R11 body, unroll 8): transposed smem tile, packed rows ----
template <int MM, int RS>
__device__ __forceinline__ void upA2_body(int blk, const float* __restrict__ x,
                                          float2* __restrict__ A, float* smraw) {
    const int HH = 2 * MM;
    const int RTOT = (256 / MM) * RS;         // 16
    float*  xs = smraw;                       // [MM][RTOT] transposed
    float2* ps = (float2*)(smraw + MM * RTOT);
    int tid = threadIdx.x;
    if (tid < MM) ps[tid] = phi_val(2 * tid + 1, MM, 1.f / (float)HH);
    int row0 = blk * RTOT;
    const float* xb = x + (size_t)row0 * MM;
#pragma unroll
    for (int i = tid; i < RTOT * MM; i += 256)
        xs[(i & (MM - 1)) * RTOT + (i / MM)] = xb[i];
    __syncthreads();
    int g = tid / MM, u = tid & (MM - 1);
    u64 arr[RS / 2], aii[RS / 2];
#pragma unroll
    for (int k = 0; k < RS / 2; ++k) { arr[k] = 0ull; aii[k] = 0ull; }
    const float* xg = xs + g * RS;
#pragma unroll 8
    for (int qy = 0; qy < MM; ++qy) {
        float2 p = ps[(u - qy) & (MM - 1)];
        u64 px2 = pack2(p.x, p.x), py2 = pack2(p.y, p.y);
        const float* col = xg + qy * RTOT;
#pragma unroll
        for (int rp = 0; rp < RS / 4; ++rp) {
            ulonglong2 vv = *(const ulonglong2*)(col + rp * 4);  // 4 rows
            fma2(arr[2 * rp],     vv.x, px2);
            fma2(arr[2 * rp + 1], vv.y, px2);
            fma2(aii[2 * rp],     vv.x, py2);
            fma2(aii[2 * rp + 1], vv.y, py2);
        }
    }
    float2* Ab = A + (size_t)row0 * HH;
#pragma unroll
    for (int k = 0; k < RS / 2; ++k) {
        float r0, r1, i0, i1;
        unpack2(arr[k], r0, r1);
        unpack2(aii[k], i0, i1);
        int rl = g * RS + 2 * k;
        Ab[(size_t)rl * HH + 2 * u + 1]       = make_float2(r0, i0);
        Ab[(size_t)(rl + 1) * HH + 2 * u + 1] = make_float2(r1, i1);
        Ab[(size_t)rl * HH + 2 * u]       = make_float2(xs[u * RTOT + rl], 0.f);
        Ab[(size_t)(rl + 1) * HH + 2 * u] = make_float2(xs[u * RTOT + rl + 1], 0.f);
    }
}

// ---- upA r=4 (R11 body, unroll 8) ----
__device__ __forceinline__ void upA4_body(int blk, const float* __restrict__ x,
                                          float2* __restrict__ A, float* smraw) {
    float*  xs = smraw;                       // [64][8] transposed
    float2* ps = (float2*)(smraw + 512);      // 192
    int tid = threadIdx.x;
    if (tid < 192)
        ps[tid] = phi_val(4 * (tid & 63) + (tid >> 6) + 1, 64, 1.f / 256.f);
    int row0 = blk * 8;
    const float* xb = x + (size_t)row0 * 64;
    for (int i = tid; i < 512; i += 256)
        xs[(i & 63) * 8 + (i >> 6)] = xb[i];
    __syncthreads();
    float2* Ab = A + (size_t)row0 * 256;
    if (tid < 192) {
        int cls = tid >> 6, u = tid & 63;
        const float2* pc = ps + cls * 64;
        u64 arr[4], aii[4];
#pragma unroll
        for (int k = 0; k < 4; ++k) { arr[k] = 0ull; aii[k] = 0ull; }
#pragma unroll 8
        for (int qy = 0; qy < 64; ++qy) {
            float2 p = pc[(u - qy) & 63];
            u64 px2 = pack2(p.x, p.x), py2 = pack2(p.y, p.y);
            const float* col = xs + qy * 8;
            ulonglong2 v0 = *(const ulonglong2*)(col);
            ulonglong2 v1 = *(const ulonglong2*)(col + 4);
            fma2(arr[0], v0.x, px2); fma2(arr[1], v0.y, px2);
            fma2(arr[2], v1.x, px2); fma2(arr[3], v1.y, px2);
            fma2(aii[0], v0.x, py2); fma2(aii[1], v0.y, py2);
            fma2(aii[2], v1.x, py2); fma2(aii[3], v1.y, py2);
        }
        int ty = 4 * u + cls + 1;
#pragma unroll
        for (int k = 0; k < 4; ++k) {
            float r0, r1, i0, i1;
            unpack2(arr[k], r0, r1);
            unpack2(aii[k], i0, i1);
            Ab[(size_t)(2 * k) * 256 + ty]     = make_float2(r0, i0);
            Ab[(size_t)(2 * k + 1) * 256 + ty] = make_float2(r1, i1);
        }
    } else {
        int u = tid - 192;
#pragma unroll
        for (int rr = 0; rr < 8; ++rr)
            Ab[(size_t)rr * 256 + 4 * u] = make_float2(xs[u * 8 + rr], 0.f);
    }
}

__global__ void __launch_bounds__(256) upA_kernel(const float* __restrict__ x1,
                                                  const float* __restrict__ x2,
                                                  float* __restrict__ out) {
    extern __shared__ float smraw[];
    int bx = blockIdx.x;
    if (bx < 21) out[bx * 256 + threadIdx.x] = 0.f;   // 21*256 = 5376 = |out|
    if (bx < 128)      upA2_body<128, 8>(bx, x1, g_A01, smraw);
    else if (bx < 256) upA4_body(bx - 128, x2, g_A02, smraw);
    else               upA2_body<64, 4>(bx - 256, x2, g_A12, smraw);
}

// ---- upB r=2 (R11 body): qx-paired, aligned LDS.128 window ----
template <int MM, int TX>   // TX must be 16
__device__ __forceinline__ void upB2_core(int img, int t0, int ty,
                                          const float2* __restrict__ A,
                                          float* __restrict__ U,
                                          const float2* ps) {
    const int HH = 2 * MM;
    u64 acc2[TX];
#pragma unroll
    for (int i = 0; i < TX; ++i) acc2[i] = 0ull;
    const float2* Ab = A + (size_t)img * MM * HH + ty;
    float* Ub = U + (size_t)img * HH * HH;
    for (int qx = 0; qx < MM; qx += 2) {
        float2 av_a = Ab[(size_t)qx * HH];
        float2 av_b = Ab[(size_t)(qx + 1) * HH];
        if ((unsigned)(qx - t0) < (unsigned)TX)
            Ub[(size_t)(2 * qx) * HH + ty] = av_a.x;
        if ((unsigned)(qx + 1 - t0) < (unsigned)TX)
            Ub[(size_t)(2 * (qx + 1)) * HH + ty] = av_b.x;
        int k0 = (t0 - qx) & (MM - 1);                 // even
        const ulonglong2* pw = (const ulonglong2*)(ps + k0);
        u64 W[16];
#pragma unroll
        for (int m2 = 0; m2 < 8; ++m2) { ulonglong2 t = pw[m2]; W[2 * m2] = t.x; W[2 * m2 + 1] = t.y; }
        u64 ea = *(const u64*)(ps + ((k0 - 1) & (MM - 1)));
        u64 a2 = pack2(av_a.x, av_a.y);
        u64 b2 = pack2(av_b.x, av_b.y);
        fma2(acc2[0], b2, ea);
#pragma unroll
        for (int i = 0; i < 16; ++i) fma2(acc2[i], a2, W[i]);
#pragma unroll
        for (int i = 1; i < 16; ++i) fma2(acc2[i], b2, W[i - 1]);
    }
#pragma unroll
    for (int i = 0; i < TX; ++i) {
        float lo, hi; unpack2(acc2[i], lo, hi);
        Ub[(size_t)(2 * (t0 + i) + 1) * HH + ty] = lo - hi;
    }
}

// ---- upB r=4 (R11 body) ----
__device__ __forceinline__ void upB4_core(int img, int t0, int cls, int ty,
                                          const float2* __restrict__ A,
                                          float* __restrict__ U,
                                          const float2* ps) {
    u64 acc2[16];
#pragma unroll
    for (int i = 0; i < 16; ++i) acc2[i] = 0ull;
    const float2* Ab = A + (size_t)img * 64 * 256 + ty;
    float* Ub = U + (size_t)img * 256 * 256;
    for (int qx = 0; qx < 64; qx += 2) {
        float2 av_a = Ab[(size_t)qx * 256];
        float2 av_b = Ab[(size_t)(qx + 1) * 256];
        if (cls == 0 && (unsigned)(qx - t0) < 16u)
            Ub[(size_t)(4 * qx) * 256 + ty] = av_a.x;
        if (cls == 0 && (unsigned)(qx + 1 - t0) < 16u)
            Ub[(size_t)(4 * (qx + 1)) * 256 + ty] = av_b.x;
        int k0 = (t0 - qx) & 63;                       // even
        const ulonglong2* pw = (const ulonglong2*)(ps + k0);
        u64 W[16];
#pragma unroll
        for (int m2 = 0; m2 < 8; ++m2) { ulonglong2 t = pw[m2]; W[2 * m2] = t.x; W[2 * m2 + 1] = t.y; }
        u64 ea = *(const u64*)(ps + ((k0 - 1) & 63));
        u64 a2 = pack2(av_a.x, av_a.y);
        u64 b2 = pack2(av_b.x, av_b.y);
        fma2(acc2[0], b2, ea);
#pragma unroll
        for (int i = 0; i < 16; ++i) fma2(acc2[i], a2, W[i]);
#pragma unroll
        for (int i = 1; i < 16; ++i) fma2(acc2[i], b2, W[i - 1]);
    }
#pragma unroll
    for (int i = 0; i < 16; ++i) {
        float lo, hi; unpack2(acc2[i], lo, hi);
        Ub[(size_t)(4 * (t0 + i) + cls + 1) * 256 + ty] = lo - hi;
    }
}

__global__ void __launch_bounds__(256) upB_kernel() {
    extern __shared__ float smraw[];
    float2* ps = (float2*)smraw;
    int bx = blockIdx.x, tid = threadIdx.x;
    if (bx < 128) {                            // upB01: MM=128, TX=16
        int img = bx >> 3, t0 = (bx & 7) * 16;
        if (tid < 128) { float2 v = phi_val(2 * tid + 1, 128, 1.f / 256.f); ps[tid] = v; ps[tid + 128] = v; }
        __syncthreads();
        upB2_core<128, 16>(img, t0, tid, g_A01, g_U01, ps);
        return;
    }
    bx -= 128;
    if (bx < 192) {                            // upB02: r=4
        int img = bx / 12, r = bx % 12, cls = r >> 2, t0 = (r & 3) * 16;
        if (tid < 64) { float2 v = phi_val(4 * tid + cls + 1, 64, 1.f / 256.f); ps[tid] = v; ps[tid + 64] = v; }
        __syncthreads();
        upB4_core(img, t0, cls, tid, g_A02, g_U02, ps);
        return;
    }
    bx -= 192;                                 // upB12: 2 images per block
    {
        int imgp = bx >> 2, t0 = (bx & 3) * 16;
        if (tid < 64) { float2 v = phi_val(2 * tid + 1, 64, 1.f / 128.f); ps[tid] = v; ps[tid + 64] = v; }
        __syncthreads();
        upB2_core<64, 16>(imgp * 2 + (tid >> 7), t0, tid & 127, g_A12, g_U12, ps);
    }
}

// ---- corr body (R11, unchanged): 2048-q chunks, 2-q vector loads ----
__device__ __forceinline__ void corr_body(const float* __restrict__ A,
                                          const float* __restrict__ B,
                                          float* __restrict__ out,
                                          int lm, int qblk, int s, int b,
                                          int sg, int trans, int pbase,
                                          float* smraw) {
    int h = 1 << lm, hh = h * h, hm = h - 1;
    int dx = sg * c_dx[s], dy = sg * c_dy[s];
    const float* Ab = A + (size_t)b * LCH * hh;
    const float* Bb = B + (size_t)b * LCH * hh;
    int q0 = qblk * 2048;
    int dyEven = !(dy & 1);
    u64 acc2[32];
#pragma unroll
    for (int k = 0; k < 32; ++k) acc2[k] = 0ull;
    for (int q = q0 + threadIdx.x * 2; q < q0 + 2048; q += 256) {
        int qx = q >> lm, qy = q & hm;                 // qy even
        int fx  = ((qx + dx) & hm) << lm;
        int fya = (qy + dy) & hm;
        int fyb = (qy + 1 + dy) & hm;
        float a_a[8], a_b[8];
        if (dyEven) {
#pragma unroll
            for (int l = 0; l < 8; ++l) {
                float2 av = *(const float2*)&Ab[(size_t)l * hh + fx + fya];
                a_a[l] = av.x; a_b[l] = av.y;
            }
        } else {
#pragma unroll
            for (int l = 0; l < 8; ++l) {
                a_a[l] = Ab[(size_t)l * hh + fx + fya];
                a_b[l] = Ab[(size_t)l * hh + fx + fyb];
            }
        }
        float2 cc[8];
#pragma unroll
        for (int j = 0; j < 8; ++j)
            cc[j] = *(const float2*)&Bb[(size_t)j * hh + q];
        u64 c2a[4], c2b[4];
#pragma unroll
        for (int jj = 0; jj < 4; ++jj) {
            c2a[jj] = pack2(cc[2 * jj].x, cc[2 * jj + 1].x);
            c2b[jj] = pack2(cc[2 * jj].y, cc[2 * jj + 1].y);
        }
#pragma unroll
        for (int i = 0; i < 8; ++i) {
            u64 a2a = pack2(a_a[i], a_a[i]);
            u64 a2b = pack2(a_b[i], a_b[i]);
#pragma unroll
            for (int jj = 0; jj < 4; ++jj) {
                fma2(acc2[i * 4 + jj], a2a, c2a[jj]);
                fma2(acc2[i * 4 + jj], a2b, c2b[jj]);
            }
        }
    }
    u64* red = (u64*)smraw;
    int lane = threadIdx.x & 31;
    int wid  = threadIdx.x >> 5;
#pragma unroll
    for (int k = 0; k < 32; ++k) {
        u64 v = acc2[k];
        v = add2(v, __shfl_down_sync(0xffffffffu, v, 16));
        v = add2(v, __shfl_down_sync(0xffffffffu, v, 8));
        v = add2(v, __shfl_down_sync(0xffffffffu, v, 4));
        v = add2(v, __shfl_down_sync(0xffffffffu, v, 2));
        v = add2(v, __shfl_down_sync(0xffffffffu, v, 1));
        if (lane == 0) red[k * 4 + wid] = v;
    }
    __syncthreads();
    if (threadIdx.x < 32) {
        u64 sum = red[threadIdx.x * 4];
        sum = add2(sum, red[threadIdx.x * 4 + 1]);
        sum = add2(sum, red[threadIdx.x * 4 + 2]);
        sum = add2(sum, red[threadIdx.x * 4 + 3]);
        float lo, hi; unpack2(sum, lo, hi);
        int i = threadIdx.x >> 2, j0 = (threadIdx.x & 3) * 2;
        int p0 = trans ? (j0 * 8 + i) : (i * 8 + j0);
        int p1 = trans ? ((j0 + 1) * 8 + i) : (i * 8 + j0 + 1);
        atomicAdd(&out[(size_t)b * 2688 + (size_t)(pbase + p0) * 7 + s], lo);
        atomicAdd(&out[(size_t)b * 2688 + (size_t)(pbase + p1) * 7 + s], hi);
    }
}

__global__ void __launch_bounds__(128) corr_kernel(const float* __restrict__ x0,
                                                   const float* __restrict__ x1,
                                                   const float* __restrict__ x2,
                                                   float* __restrict__ out) {
    extern __shared__ float smraw[];
    int bx = blockIdx.x, s = blockIdx.y, b = blockIdx.z;
    if (bx < 32)       corr_body(x0,    x0, out, 8, bx,       s, b,  1, 0, 0,   smraw);
    else if (bx < 64)  corr_body(g_U01, x0, out, 8, bx - 32,  s, b, -1, 1, 64,  smraw);
    else if (bx < 96)  corr_body(g_U02, x0, out, 8, bx - 64,  s, b, -1, 1, 128, smraw);
    else if (bx < 104) corr_body(x1,    x1, out, 7, bx - 96,  s, b,  1, 0, 192, smraw);
    else if (bx < 112) corr_body(g_U12, x1, out, 7, bx - 104, s, b, -1, 1, 256, smraw);
    else               corr_body(x2,    x2, out, 6, bx - 112, s, b,  1, 0, 320, smraw);
}

extern "C" void kernel_launch(void* const* d_in, const int* in_sizes, int n_in,
                              void* d_out, int out_size) {
    const float* x0 = nullptr;
    const float* x1 = nullptr;
    const float* x2 = nullptr;
    for (int i = 0; i < n_in; ++i) {
        if (in_sizes[i] == 2 * 8 * 256 * 256)      x0 = (const float*)d_in[i];
        else if (in_sizes[i] == 2 * 8 * 128 * 128) x1 = (const float*)d_in[i];
        else if (in_sizes[i] == 2 * 8 * 64 * 64)   x2 = (const float*)d_in[i];
    }
    float* out = (float*)d_out;

    upA_kernel<<<320, 256, 9216>>>(x1, x2, out);       // also zeroes d_out
    upB_kernel<<<352, 256, 2048>>>();
    corr_kernel<<<dim3(114, 7, 2), 128, 1024>>>(x0, x1, x2, out);
}

// round 15
// speedup vs baseline: 1.1241x; 1.0204x over previous
#include <cuda_runtime.h>
#include <math.h>

// ---------------------------------------------------------------------------
// corr[u] = Sum_t x1[t] * Re(U[(t-u) mod h]),  U = separable Dirichlet
// upsample of the coarser x2.  For h = r*m, phi(t)=0 when t%r==0 (t!=0),
// phi(0)=1 -> outputs t%r==0 are copies; others use compacted residue tables.
// phi(t) = (1/m) e^{-i pi t/h} sin(pi t m/h)/sin(pi t/h), exact via sinpif.
// R14 = R11 with: (a) d_out zeroing folded into upA (drops the memset launch
// node), (b) upA qy unroll 4 -> 8 (deeper LDS pipelining).
// Output [2, 6*64, 7]; shifts (0,0),(0,1),(0,2),(1,0),(1,1),(2,0),(-1,1).
// ---------------------------------------------------------------------------

#define LCH 8
typedef unsigned long long u64;

__device__ float2 g_A01[16 * 128 * 256]; // y-upsampled (complex)
__device__ float2 g_A02[16 * 64 * 256];
__device__ float2 g_A12[16 * 64 * 128];
__device__ float  g_U01[16 * 256 * 256]; // fully upsampled (real)
__device__ float  g_U02[16 * 256 * 256];
__device__ float  g_U12[16 * 128 * 128];

__constant__ int c_dx[7] = {0, 0, 0, 1, 1, 2, -1};
__constant__ int c_dy[7] = {0, 1, 2, 0, 1, 0, 1};

__device__ __forceinline__ u64 pack2(float lo, float hi) {
    u64 r; asm("mov.b64 %0, {%1, %2};" : "=l"(r) : "f"(lo), "f"(hi)); return r;
}
__device__ __forceinline__ void unpack2(u64 v, float& lo, float& hi) {
    asm("mov.b64 {%0, %1}, %2;" : "=f"(lo), "=f"(hi) : "l"(v));
}
__device__ __forceinline__ void fma2(u64& d, u64 a, u64 b) {
    asm("fma.rn.f32x2 %0, %1, %2, %3;" : "=l"(d) : "l"(a), "l"(b), "l"(d));
}
__device__ __forceinline__ u64 add2(u64 a, u64 b) {
    u64 r; asm("add.rn.f32x2 %0, %1, %2;" : "=l"(r) : "l"(a), "l"(b)); return r;
}

__device__ __forceinline__ float2 phi_val(int t, int m, float inv_h) {
    float a  = (float)t * inv_h;              // exact binary fraction
    float sm = sinpif((float)m * a);
    float sd = sinpif(a);
    float s  = sm / (sd * (float)m);
    return make_float2(cospif(a) * s, -sm / (float)m);
}

// ---- upA r=2 (R11 body, unroll 8): transposed smem tile, packed rows ----
template <int MM, int RS>
__device__ __forceinline__ void upA2_body(int blk, const float* __restrict__ x,
                                          float2* __restrict__ A, float* smraw) {
    const int HH = 2 * MM;
    const int RTOT = (256 / MM) * RS;         // 16
    float*  xs = smraw;                       // [MM][RTOT] transposed
    float2* ps = (float2*)(smraw + MM * RTOT);
    int tid = threadIdx.x;
    if (tid < MM) ps[tid] = phi_val(2 * tid + 1, MM, 1.f / (float)HH);
    int row0 = blk * RTOT;
    const float* xb = x + (size_t)row0 * MM;
#pragma unroll
    for (int i = tid; i < RTOT * MM; i += 256)
        xs[(i & (MM - 1)) * RTOT + (i / MM)] = xb[i];
    __syncthreads();
    int g = tid / MM, u = tid & (MM - 1);
    u64 arr[RS / 2], aii[RS / 2];
#pragma unroll
    for (int k = 0; k < RS / 2; ++k) { arr[k] = 0ull; aii[k] = 0ull; }
    const float* xg = xs + g * RS;
#pragma unroll 8
    for (int qy = 0; qy < MM; ++qy) {
        float2 p = ps[(u - qy) & (MM - 1)];
        u64 px2 = pack2(p.x, p.x), py2 = pack2(p.y, p.y);
        const float* col = xg + qy * RTOT;
#pragma unroll
        for (int rp = 0; rp < RS / 4; ++rp) {
            ulonglong2 vv = *(const ulonglong2*)(col + rp * 4);  // 4 rows
            fma2(arr[2 * rp],     vv.x, px2);
            fma2(arr[2 * rp + 1], vv.y, px2);
            fma2(aii[2 * rp],     vv.x, py2);
            fma2(aii[2 * rp + 1], vv.y, py2);
        }
    }
    float2* Ab = A + (size_t)row0 * HH;
#pragma unroll
    for (int k = 0; k < RS / 2; ++k) {
        float r0, r1, i0, i1;
        unpack2(arr[k], r0, r1);
        unpack2(aii[k], i0, i1);
        int rl = g * RS + 2 * k;
        Ab[(size_t)rl * HH + 2 * u + 1]       = make_float2(r0, i0);
        Ab[(size_t)(rl + 1) * HH + 2 * u + 1] = make_float2(r1, i1);
        Ab[(size_t)rl * HH + 2 * u]       = make_float2(xs[u * RTOT + rl], 0.f);
        Ab[(size_t)(rl + 1) * HH + 2 * u] = make_float2(xs[u * RTOT + rl + 1], 0.f);
    }
}

// ---- upA r=4 (R11 body, unroll 8) ----
__device__ __forceinline__ void upA4_body(int blk, const float* __restrict__ x,
                                          float2* __restrict__ A, float* smraw) {
    float*  xs = smraw;                       // [64][8] transposed
    float2* ps = (float2*)(smraw + 512);      // 192
    int tid = threadIdx.x;
    if (tid < 192)
        ps[tid] = phi_val(4 * (tid & 63) + (tid >> 6) + 1, 64, 1.f / 256.f);
    int row0 = blk * 8;
    const float* xb = x + (size_t)row0 * 64;
    for (int i = tid; i < 512; i += 256)
        xs[(i & 63) * 8 + (i >> 6)] = xb[i];
    __syncthreads();
    float2* Ab = A + (size_t)row0 * 256;
    if (tid < 192) {
        int cls = tid >> 6, u = tid & 63;
        const float2* pc = ps + cls * 64;
        u64 arr[4], aii[4];
#pragma unroll
        for (int k = 0; k < 4; ++k) { arr[k] = 0ull; aii[k] = 0ull; }
#pragma unroll 8
        for (int qy = 0; qy < 64; ++qy) {
            float2 p = pc[(u - qy) & 63];
            u64 px2 = pack2(p.x, p.x), py2 = pack2(p.y, p.y);
            const float* col = xs + qy * 8;
            ulonglong2 v0 = *(const ulonglong2*)(col);
            ulonglong2 v1 = *(const ulonglong2*)(col + 4);
            fma2(arr[0], v0.x, px2); fma2(arr[1], v0.y, px2);
            fma2(arr[2], v1.x, px2); fma2(arr[3], v1.y, px2);
            fma2(aii[0], v0.x, py2); fma2(aii[1], v0.y, py2);
            fma2(aii[2], v1.x, py2); fma2(aii[3], v1.y, py2);
        }
        int ty = 4 * u + cls + 1;
#pragma unroll
        for (int k = 0; k < 4; ++k) {
            float r0, r1, i0, i1;
            unpack2(arr[k], r0, r1);
            unpack2(aii[k], i0, i1);
            Ab[(size_t)(2 * k) * 256 + ty]     = make_float2(r0, i0);
            Ab[(size_t)(2 * k + 1) * 256 + ty] = make_float2(r1, i1);
        }
    } else {
        int u = tid - 192;
#pragma unroll
        for (int rr = 0; rr < 8; ++rr)
            Ab[(size_t)rr * 256 + 4 * u] = make_float2(xs[u * 8 + rr], 0.f);
    }
}

__global__ void __launch_bounds__(256) upA_kernel(const float* __restrict__ x1,
                                                  const float* __restrict__ x2,
                                                  float* __restrict__ out) {
    extern __shared__ float smraw[];
    int bx = blockIdx.x;
    if (bx < 21) out[bx * 256 + threadIdx.x] = 0.f;   // 21*256 = 5376 = |out|
    if (bx < 128)      upA2_body<128, 8>(bx, x1, g_A01, smraw);
    else if (bx < 256) upA4_body(bx - 128, x2, g_A02, smraw);
    else               upA2_body<64, 4>(bx - 256, x2, g_A12, smraw);
}

// ---- upB r=2 (R11 body): qx-paired, aligned LDS.128 window ----
template <int MM, int TX>   // TX must be 16
__device__ __forceinline__ void upB2_core(int img, int t0, int ty,
                                          const float2* __restrict__ A,
                                          float* __restrict__ U,
                                          const float2* ps) {
    const int HH = 2 * MM;
    u64 acc2[TX];
#pragma unroll
    for (int i = 0; i < TX; ++i) acc2[i] = 0ull;
    const float2* Ab = A + (size_t)img * MM * HH + ty;
    float* Ub = U + (size_t)img * HH * HH;
    for (int qx = 0; qx < MM; qx += 2) {
        float2 av_a = Ab[(size_t)qx * HH];
        float2 av_b = Ab[(size_t)(qx + 1) * HH];
        if ((unsigned)(qx - t0) < (unsigned)TX)
            Ub[(size_t)(2 * qx) * HH + ty] = av_a.x;
        if ((unsigned)(qx + 1 - t0) < (unsigned)TX)
            Ub[(size_t)(2 * (qx + 1)) * HH + ty] = av_b.x;
        int k0 = (t0 - qx) & (MM - 1);                 // even
        const ulonglong2* pw = (const ulonglong2*)(ps + k0);
        u64 W[16];
#pragma unroll
        for (int m2 = 0; m2 < 8; ++m2) { ulonglong2 t = pw[m2]; W[2 * m2] = t.x; W[2 * m2 + 1] = t.y; }
        u64 ea = *(const u64*)(ps + ((k0 - 1) & (MM - 1)));
        u64 a2 = pack2(av_a.x, av_a.y);
        u64 b2 = pack2(av_b.x, av_b.y);
        fma2(acc2[0], b2, ea);
#pragma unroll
        for (int i = 0; i < 16; ++i) fma2(acc2[i], a2, W[i]);
#pragma unroll
        for (int i = 1; i < 16; ++i) fma2(acc2[i], b2, W[i - 1]);
    }
#pragma unroll
    for (int i = 0; i < TX; ++i) {
        float lo, hi; unpack2(acc2[i], lo, hi);
        Ub[(size_t)(2 * (t0 + i) + 1) * HH + ty] = lo - hi;
    }
}

// ---- upB r=4 (R11 body) ----
__device__ __forceinline__ void upB4_core(int img, int t0, int cls, int ty,
                                          const float2* __restrict__ A,
                                          float* __restrict__ U,
                                          const float2* ps) {
    u64 acc2[16];
#pragma unroll
    for (int i = 0; i < 16; ++i) acc2[i] = 0ull;
    const float2* Ab = A + (size_t)img * 64 * 256 + ty;
    float* Ub = U + (size_t)img * 256 * 256;
    for (int qx = 0; qx < 64; qx += 2) {
        float2 av_a = Ab[(size_t)qx * 256];
        float2 av_b = Ab[(size_t)(qx + 1) * 256];
        if (cls == 0 && (unsigned)(qx - t0) < 16u)
            Ub[(size_t)(4 * qx) * 256 + ty] = av_a.x;
        if (cls == 0 && (unsigned)(qx + 1 - t0) < 16u)
            Ub[(size_t)(4 * (qx + 1)) * 256 + ty] = av_b.x;
        int k0 = (t0 - qx) & 63;                       // even
        const ulonglong2* pw = (const ulonglong2*)(ps + k0);
        u64 W[16];
#pragma unroll
        for (int m2 = 0; m2 < 8; ++m2) { ulonglong2 t = pw[m2]; W[2 * m2] = t.x; W[2 * m2 + 1] = t.y; }
        u64 ea = *(const u64*)(ps + ((k0 - 1) & 63));
        u64 a2 = pack2(av_a.x, av_a.y);
        u64 b2 = pack2(av_b.x, av_b.y);
        fma2(acc2[0], b2, ea);
#pragma unroll
        for (int i = 0; i < 16; ++i) fma2(acc2[i], a2, W[i]);
#pragma unroll
        for (int i = 1; i < 16; ++i) fma2(acc2[i], b2, W[i - 1]);
    }
#pragma unroll
    for (int i = 0; i < 16; ++i) {
        float lo, hi; unpack2(acc2[i], lo, hi);
        Ub[(size_t)(4 * (t0 + i) + cls + 1) * 256 + ty] = lo - hi;
    }
}

__global__ void __launch_bounds__(256) upB_kernel() {
    extern __shared__ float smraw[];
    float2* ps = (float2*)smraw;
    int bx = blockIdx.x, tid = threadIdx.x;
    if (bx < 128) {                            // upB01: MM=128, TX=16
        int img = bx >> 3, t0 = (bx & 7) * 16;
        if (tid < 128) { float2 v = phi_val(2 * tid + 1, 128, 1.f / 256.f); ps[tid] = v; ps[tid + 128] = v; }
        __syncthreads();
        upB2_core<128, 16>(img, t0, tid, g_A01, g_U01, ps);
        return;
    }
    bx -= 128;
    if (bx < 192) {                            // upB02: r=4
        int img = bx / 12, r = bx % 12, cls = r >> 2, t0 = (r & 3) * 16;
        if (tid < 64) { float2 v = phi_val(4 * tid + cls + 1, 64, 1.f / 256.f); ps[tid] = v; ps[tid + 64] = v; }
        __syncthreads();
        upB4_core(img, t0, cls, tid, g_A02, g_U02, ps);
        return;
    }
    bx -= 192;                                 // upB12: 2 images per block
    {
        int imgp = bx >> 2, t0 = (bx & 3) * 16;
        if (tid < 64) { float2 v = phi_val(2 * tid + 1, 64, 1.f / 128.f); ps[tid] = v; ps[tid + 64] = v; }
        __syncthreads();
        upB2_core<64, 16>(imgp * 2 + (tid >> 7), t0, tid & 127, g_A12, g_U12, ps);
    }
}

// ---- corr body (R11, unchanged): 2048-q chunks, 2-q vector loads ----
__device__ __forceinline__ void corr_body(const float* __restrict__ A,
                                          const float* __restrict__ B,
                                          float* __restrict__ out,
                                          int lm, int qblk, int s, int b,
                                          int sg, int trans, int pbase,
                                          float* smraw) {
    int h = 1 << lm, hh = h * h, hm = h - 1;
    int dx = sg * c_dx[s], dy = sg * c_dy[s];
    const float* Ab = A + (size_t)b * LCH * hh;
    const float* Bb = B + (size_t)b * LCH * hh;
    int q0 = qblk * 2048;
    int dyEven = !(dy & 1);
    u64 acc2[32];
#pragma unroll
    for (int k = 0; k < 32; ++k) acc2[k] = 0ull;
    for (int q = q0 + threadIdx.x * 2; q < q0 + 2048; q += 256) {
        int qx = q >> lm, qy = q & hm;                 // qy even
        int fx  = ((qx + dx) & hm) << lm;
        int fya = (qy + dy) & hm;
        int fyb = (qy + 1 + dy) & hm;
        float a_a[8], a_b[8];
        if (dyEven) {
#pragma unroll
            for (int l = 0; l < 8; ++l) {
                float2 av = *(const float2*)&Ab[(size_t)l * hh + fx + fya];
                a_a[l] = av.x; a_b[l] = av.y;
            }
        } else {
#pragma unroll
            for (int l = 0; l < 8; ++l) {
                a_a[l] = Ab[(size_t)l * hh + fx + fya];
                a_b[l] = Ab[(size_t)l * hh + fx + fyb];
            }
        }
        float2 cc[8];
#pragma unroll
        for (int j = 0; j < 8; ++j)
            cc[j] = *(const float2*)&Bb[(size_t)j * hh + q];
        u64 c2a[4], c2b[4];
#pragma unroll
        for (int jj = 0; jj < 4; ++jj) {
            c2a[jj] = pack2(cc[2 * jj].x, cc[2 * jj + 1].x);
            c2b[jj] = pack2(cc[2 * jj].y, cc[2 * jj + 1].y);
        }
#pragma unroll
        for (int i = 0; i < 8; ++i) {
            u64 a2a = pack2(a_a[i], a_a[i]);
            u64 a2b = pack2(a_b[i], a_b[i]);
#pragma unroll
            for (int jj = 0; jj < 4; ++jj) {
                fma2(acc2[i * 4 + jj], a2a, c2a[jj]);
                fma2(acc2[i * 4 + jj], a2b, c2b[jj]);
            }
        }
    }
    u64* red = (u64*)smraw;
    int lane = threadIdx.x & 31;
    int wid  = threadIdx.x >> 5;
#pragma unroll
    for (int k = 0; k < 32; ++k) {
        u64 v = acc2[k];
        v = add2(v, __shfl_down_sync(0xffffffffu, v, 16));
        v = add2(v, __shfl_down_sync(0xffffffffu, v, 8));
        v = add2(v, __shfl_down_sync(0xffffffffu, v, 4));
        v = add2(v, __shfl_down_sync(0xffffffffu, v, 2));
        v = add2(v, __shfl_down_sync(0xffffffffu, v, 1));
        if (lane == 0) red[k * 4 + wid] = v;
    }
    __syncthreads();
    if (threadIdx.x < 32) {
        u64 sum = red[threadIdx.x * 4];
        sum = add2(sum, red[threadIdx.x * 4 + 1]);
        sum = add2(sum, red[threadIdx.x * 4 + 2]);
        sum = add2(sum, red[threadIdx.x * 4 + 3]);
        float lo, hi; unpack2(sum, lo, hi);
        int i = threadIdx.x >> 2, j0 = (threadIdx.x & 3) * 2;
        int p0 = trans ? (j0 * 8 + i) : (i * 8 + j0);
        int p1 = trans ? ((j0 + 1) * 8 + i) : (i * 8 + j0 + 1);
        atomicAdd(&out[(size_t)b * 2688 + (size_t)(pbase + p0) * 7 + s], lo);
        atomicAdd(&out[(size_t)b * 2688 + (size_t)(pbase + p1) * 7 + s], hi);
    }
}

__global__ void __launch_bounds__(128) corr_kernel(const float* __restrict__ x0,
                                                   const float* __restrict__ x1,
                                                   const float* __restrict__ x2,
                                                   float* __restrict__ out) {
    extern __shared__ float smraw[];
    int bx = blockIdx.x, s = blockIdx.y, b = blockIdx.z;
    if (bx < 32)       corr_body(x0,    x0, out, 8, bx,       s, b,  1, 0, 0,   smraw);
    else if (bx < 64)  corr_body(g_U01, x0, out, 8, bx - 32,  s, b, -1, 1, 64,  smraw);
    else if (bx < 96)  corr_body(g_U02, x0, out, 8, bx - 64,  s, b, -1, 1, 128, smraw);
    else if (bx < 104) corr_body(x1,    x1, out, 7, bx - 96,  s, b,  1, 0, 192, smraw);
    else if (bx < 112) corr_body(g_U12, x1, out, 7, bx - 104, s, b, -1, 1, 256, smraw);
    else               corr_body(x2,    x2, out, 6, bx - 112, s, b,  1, 0, 320, smraw);
}

extern "C" void kernel_launch(void* const* d_in, const int* in_sizes, int n_in,
                              void* d_out, int out_size) {
    const float* x0 = nullptr;
    const float* x1 = nullptr;
    const float* x2 = nullptr;
    for (int i = 0; i < n_in; ++i) {
        if (in_sizes[i] == 2 * 8 * 256 * 256)      x0 = (const float*)d_in[i];
        else if (in_sizes[i] == 2 * 8 * 128 * 128) x1 = (const float*)d_in[i];
        else if (in_sizes[i] == 2 * 8 * 64 * 64)   x2 = (const float*)d_in[i];
    }
    float* out = (float*)d_out;

    upA_kernel<<<320, 256, 9216>>>(x1, x2, out);       // also zeroes d_out
    upB_kernel<<<352, 256, 2048>>>();
    corr_kernel<<<dim3(114, 7, 2), 128, 1024>>>(x0, x1, x2, out);
}